// round 1
// baseline (speedup 1.0000x reference)
#include <cuda_runtime.h>
#include <math.h>

// Problem constants
#define BB   8
#define SQL  256
#define SKV  1024
#define DM   1024
#define NH   16
#define DKH  64
#define DFF  4096

#define QROWS  (BB*SQL)      // 2048
#define KVROWS (BB*SKV)      // 8192
#define OUT_ELEMS  ((size_t)QROWS*DM)           // 2,097,152
#define ATTN_ELEMS ((size_t)BB*NH*SQL*SKV)      // 33,554,432

// ---------------- scratch (static device globals; no allocation) ----------------
__device__ float g_qln [QROWS*DM];
__device__ float g_kvln[KVROWS*DM];
__device__ float g_Qp  [QROWS*DM];
__device__ float g_Kp  [KVROWS*DM];
__device__ float g_Vp  [KVROWS*DM];
__device__ float g_ctx [QROWS*DM];
__device__ float g_x   [QROWS*DM];
__device__ float g_y   [QROWS*DM];
__device__ float g_h   [QROWS*DFF];
__device__ float g_attn_fb[BB*NH*SQL*SKV];   // fallback if harness output has no attn region

// ---------------- LayerNorm: one block per row, D=1024, 256 threads ----------------
__global__ void __launch_bounds__(256) ln_kernel(const float* __restrict__ x,
                                                 const float* __restrict__ g,
                                                 const float* __restrict__ b,
                                                 float* __restrict__ y) {
    __shared__ float ssum[256];
    __shared__ float ssq [256];
    const int row = blockIdx.x;
    const int tid = threadIdx.x;
    const float4 xv = ((const float4*)(x + (size_t)row*DM))[tid];
    float s  = xv.x + xv.y + xv.z + xv.w;
    float q2 = xv.x*xv.x + xv.y*xv.y + xv.z*xv.z + xv.w*xv.w;
    ssum[tid] = s; ssq[tid] = q2;
    __syncthreads();
    for (int st = 128; st > 0; st >>= 1) {
        if (tid < st) { ssum[tid] += ssum[tid+st]; ssq[tid] += ssq[tid+st]; }
        __syncthreads();
    }
    const float mu  = ssum[0] * (1.0f/DM);
    const float var = ssq[0]  * (1.0f/DM) - mu*mu;
    const float inv = rsqrtf(var + 1e-5f);
    const float4 gv = ((const float4*)g)[tid];
    const float4 bv = ((const float4*)b)[tid];
    float4 o;
    o.x = (xv.x - mu)*inv*gv.x + bv.x;
    o.y = (xv.y - mu)*inv*gv.y + bv.y;
    o.z = (xv.z - mu)*inv*gv.z + bv.z;
    o.w = (xv.w - mu)*inv*gv.w + bv.w;
    ((float4*)(y + (size_t)row*DM))[tid] = o;
}

// ---------------- Generic SGEMM: C[M,N] = A[M,K] @ W[K,N] + bias (+epilogue) ----------
// BM=BN=128, BK=8, 256 threads, 8x8 per thread. M%128==0, N%128==0, K%8==0.
// mode: 0 = bias only, 1 = bias + erf-GELU, 2 = bias + residual add
__global__ void __launch_bounds__(256) sgemm_kernel(const float* __restrict__ A,
                                                    const float* __restrict__ W,
                                                    const float* __restrict__ bias,
                                                    const float* __restrict__ res,
                                                    float* __restrict__ C,
                                                    int M, int N, int K, int mode) {
    __shared__ float As[8][128];
    __shared__ float Bs[8][128];
    const int tid = threadIdx.x;
    const int tx = tid & 15, ty = tid >> 4;
    const int bm = blockIdx.y, bn = blockIdx.x;

    const int arow = tid >> 1;            // 0..127
    const int acol = (tid & 1) * 4;       // 0 or 4
    const int brow = tid >> 5;            // 0..7
    const int bcol = (tid & 31) * 4;      // 0..124

    const float* Aptr = A + (size_t)(bm*128 + arow)*K + acol;
    const float* Bptr = W + (size_t)brow*N + (size_t)bn*128 + bcol;

    float acc[8][8];
    #pragma unroll
    for (int i = 0; i < 8; ++i)
        #pragma unroll
        for (int j = 0; j < 8; ++j) acc[i][j] = 0.f;

    for (int k0 = 0; k0 < K; k0 += 8) {
        float4 av = *(const float4*)(Aptr + k0);
        float4 bv = *(const float4*)(Bptr + (size_t)k0*N);
        As[acol+0][arow] = av.x;
        As[acol+1][arow] = av.y;
        As[acol+2][arow] = av.z;
        As[acol+3][arow] = av.w;
        *(float4*)&Bs[brow][bcol] = bv;
        __syncthreads();
        #pragma unroll
        for (int k = 0; k < 8; ++k) {
            float a[8], bb[8];
            *(float4*)(a)    = *(const float4*)&As[k][ty*4];
            *(float4*)(a+4)  = *(const float4*)&As[k][64 + ty*4];
            *(float4*)(bb)   = *(const float4*)&Bs[k][tx*4];
            *(float4*)(bb+4) = *(const float4*)&Bs[k][64 + tx*4];
            #pragma unroll
            for (int i = 0; i < 8; ++i)
                #pragma unroll
                for (int j = 0; j < 8; ++j)
                    acc[i][j] = fmaf(a[i], bb[j], acc[i][j]);
        }
        __syncthreads();
    }

    #pragma unroll
    for (int i = 0; i < 8; ++i) {
        const int mrow = bm*128 + ((i < 4) ? (ty*4 + i) : (64 + ty*4 + i - 4));
        #pragma unroll
        for (int j = 0; j < 8; ++j) {
            const int ncol = bn*128 + ((j < 4) ? (tx*4 + j) : (64 + tx*4 + j - 4));
            float v = acc[i][j] + bias[ncol];
            if (mode == 1) v = 0.5f * v * (1.0f + erff(v * 0.70710678118654752f));
            else if (mode == 2) v += res[(size_t)mrow*N + ncol];
            C[(size_t)mrow*N + ncol] = v;
        }
    }
}

// ---------------- attention scores: logits[bh, q, k] = Q.K / 8 ----------------
// grid: (SKV/64, SQ/64, B*H), 256 threads, 64x64 tile, K-dim = 64 (whole head)
__global__ void __launch_bounds__(256) scores_kernel(const float* __restrict__ Q,
                                                     const float* __restrict__ Km,
                                                     float* __restrict__ attn) {
    __shared__ float Qs[64][68];  // [k][m]
    __shared__ float Ks[64][68];  // [k][n]
    const int bh = blockIdx.z;
    const int b = bh >> 4, h = bh & 15;
    const int q0 = blockIdx.y * 64;
    const int n0 = blockIdx.x * 64;
    const int tid = threadIdx.x;
    const int r  = tid & 63;
    const int cg = tid >> 6;   // 0..3

    const float* qrow = Q  + (size_t)(b*SQL + q0 + r)*DM + h*DKH;
    const float* krow = Km + (size_t)(b*SKV + n0 + r)*DM + h*DKH;
    #pragma unroll
    for (int c4 = 0; c4 < 16; c4 += 4) {
        const int c = cg*16 + c4;
        float4 v = *(const float4*)(qrow + c);
        Qs[c+0][r]=v.x; Qs[c+1][r]=v.y; Qs[c+2][r]=v.z; Qs[c+3][r]=v.w;
        float4 w = *(const float4*)(krow + c);
        Ks[c+0][r]=w.x; Ks[c+1][r]=w.y; Ks[c+2][r]=w.z; Ks[c+3][r]=w.w;
    }
    __syncthreads();

    const int tx = tid & 15, ty = tid >> 4;
    float acc[4][4];
    #pragma unroll
    for (int i=0;i<4;++i) { acc[i][0]=0;acc[i][1]=0;acc[i][2]=0;acc[i][3]=0; }
    #pragma unroll 8
    for (int k = 0; k < 64; ++k) {
        float4 a = *(const float4*)&Qs[k][ty*4];
        float4 v = *(const float4*)&Ks[k][tx*4];
        float aa[4] = {a.x,a.y,a.z,a.w};
        float bb[4] = {v.x,v.y,v.z,v.w};
        #pragma unroll
        for (int i=0;i<4;++i)
            #pragma unroll
            for (int j=0;j<4;++j) acc[i][j] = fmaf(aa[i], bb[j], acc[i][j]);
    }
    #pragma unroll
    for (int i=0;i<4;++i) {
        float* out = attn + ((size_t)bh*SQL + q0 + ty*4 + i)*SKV + n0 + tx*4;
        #pragma unroll
        for (int j=0;j<4;++j) out[j] = acc[i][j] * 0.125f;
    }
}

// ---------------- row softmax in place: rows of length SKV=1024 ----------------
__global__ void __launch_bounds__(256) softmax_kernel(float* __restrict__ attn) {
    __shared__ float red[256];
    const size_t row = blockIdx.x;
    float4* p = (float4*)(attn + row*(size_t)SKV);
    const int tid = threadIdx.x;
    float4 v = p[tid];
    float m = fmaxf(fmaxf(v.x, v.y), fmaxf(v.z, v.w));
    red[tid] = m; __syncthreads();
    for (int st = 128; st > 0; st >>= 1) {
        if (tid < st) red[tid] = fmaxf(red[tid], red[tid+st]);
        __syncthreads();
    }
    m = red[0];
    __syncthreads();
    v.x = __expf(v.x - m); v.y = __expf(v.y - m);
    v.z = __expf(v.z - m); v.w = __expf(v.w - m);
    red[tid] = v.x + v.y + v.z + v.w; __syncthreads();
    for (int st = 128; st > 0; st >>= 1) {
        if (tid < st) red[tid] += red[tid+st];
        __syncthreads();
    }
    const float inv = 1.0f / red[0];
    v.x *= inv; v.y *= inv; v.z *= inv; v.w *= inv;
    p[tid] = v;
}

// ---------------- ctx = attn @ V per head: [256,64] = [256,1024]@[1024,64] ----------
// grid: (SQ/64, B*H), 256 threads, 64x64 output tile (covers whole DK)
__global__ void __launch_bounds__(256) ctx_kernel(const float* __restrict__ attn,
                                                  const float* __restrict__ V,
                                                  float* __restrict__ ctx) {
    __shared__ float As[64][68];  // [k][m]
    __shared__ float Vs[64][68];  // [k][n]
    const int bh = blockIdx.y;
    const int b = bh >> 4, h = bh & 15;
    const int q0 = blockIdx.x * 64;
    const int tid = threadIdx.x;
    const int r  = tid & 63;
    const int cg = tid >> 6;
    const int tx = tid & 15, ty = tid >> 4;

    float acc[4][4];
    #pragma unroll
    for (int i=0;i<4;++i) { acc[i][0]=0;acc[i][1]=0;acc[i][2]=0;acc[i][3]=0; }

    for (int k0 = 0; k0 < SKV; k0 += 64) {
        const float* ar = attn + ((size_t)bh*SQL + q0 + r)*SKV + k0;
        const float* vr = V + (size_t)(b*SKV + k0 + r)*DM + h*DKH;
        #pragma unroll
        for (int c4 = 0; c4 < 16; c4 += 4) {
            const int c = cg*16 + c4;
            float4 a = *(const float4*)(ar + c);
            As[c+0][r]=a.x; As[c+1][r]=a.y; As[c+2][r]=a.z; As[c+3][r]=a.w;
            *(float4*)&Vs[r][c] = *(const float4*)(vr + c);
        }
        __syncthreads();
        #pragma unroll 8
        for (int k = 0; k < 64; ++k) {
            float4 a = *(const float4*)&As[k][ty*4];
            float4 v = *(const float4*)&Vs[k][tx*4];
            float aa[4] = {a.x,a.y,a.z,a.w};
            float bb[4] = {v.x,v.y,v.z,v.w};
            #pragma unroll
            for (int i=0;i<4;++i)
                #pragma unroll
                for (int j=0;j<4;++j) acc[i][j] = fmaf(aa[i], bb[j], acc[i][j]);
        }
        __syncthreads();
    }
    #pragma unroll
    for (int i=0;i<4;++i) {
        float* out = ctx + (size_t)(b*SQL + q0 + ty*4 + i)*DM + h*DKH + tx*4;
        #pragma unroll
        for (int j=0;j<4;++j) out[j] = acc[i][j];
    }
}

// ---------------- launch ----------------
extern "C" void kernel_launch(void* const* d_in, const int* in_sizes, int n_in,
                              void* d_out, int out_size) {
    const float* memory = (const float*)d_in[0];
    const float* q      = (const float*)d_in[1];
    const float* Wq = (const float*)d_in[2];  const float* bq = (const float*)d_in[3];
    const float* Wk = (const float*)d_in[4];  const float* bk = (const float*)d_in[5];
    const float* Wv = (const float*)d_in[6];  const float* bv = (const float*)d_in[7];
    const float* Wo = (const float*)d_in[8];  const float* bo = (const float*)d_in[9];
    const float* g_kv = (const float*)d_in[10]; const float* b_kv = (const float*)d_in[11];
    const float* g_q  = (const float*)d_in[12]; const float* b_q  = (const float*)d_in[13];
    const float* g_ff = (const float*)d_in[14]; const float* b_ff = (const float*)d_in[15];
    const float* W1 = (const float*)d_in[16]; const float* b1 = (const float*)d_in[17];
    const float* W2 = (const float*)d_in[18]; const float* b2 = (const float*)d_in[19];

    float *p_qln, *p_kvln, *p_Q, *p_K, *p_V, *p_ctx, *p_x, *p_y, *p_h, *p_attn_fb;
    cudaGetSymbolAddress((void**)&p_qln,  g_qln);
    cudaGetSymbolAddress((void**)&p_kvln, g_kvln);
    cudaGetSymbolAddress((void**)&p_Q,    g_Qp);
    cudaGetSymbolAddress((void**)&p_K,    g_Kp);
    cudaGetSymbolAddress((void**)&p_V,    g_Vp);
    cudaGetSymbolAddress((void**)&p_ctx,  g_ctx);
    cudaGetSymbolAddress((void**)&p_x,    g_x);
    cudaGetSymbolAddress((void**)&p_y,    g_y);
    cudaGetSymbolAddress((void**)&p_h,    g_h);
    cudaGetSymbolAddress((void**)&p_attn_fb, g_attn_fb);

    float* out = (float*)d_out;
    float* attn = ((size_t)out_size >= OUT_ELEMS + ATTN_ELEMS) ? (out + OUT_ELEMS)
                                                               : p_attn_fb;

    // 1-2. pre-norms
    ln_kernel<<<KVROWS, 256>>>(memory, g_kv, b_kv, p_kvln);
    ln_kernel<<<QROWS,  256>>>(q,      g_q,  b_q,  p_qln);

    // 3-5. QKV projections
    sgemm_kernel<<<dim3(DM/128, QROWS/128),  256>>>(p_qln,  Wq, bq, nullptr, p_Q, QROWS,  DM, DM, 0);
    sgemm_kernel<<<dim3(DM/128, KVROWS/128), 256>>>(p_kvln, Wk, bk, nullptr, p_K, KVROWS, DM, DM, 0);
    sgemm_kernel<<<dim3(DM/128, KVROWS/128), 256>>>(p_kvln, Wv, bv, nullptr, p_V, KVROWS, DM, DM, 0);

    // 6. attention logits -> attn region
    scores_kernel<<<dim3(SKV/64, SQL/64, BB*NH), 256>>>(p_Q, p_K, attn);

    // 7. softmax in place
    softmax_kernel<<<BB*NH*SQL, 256>>>(attn);

    // 8. ctx = attn @ V
    ctx_kernel<<<dim3(SQL/64, BB*NH), 256>>>(attn, p_V, p_ctx);

    // 9. x = ctx @ Wo + bo
    sgemm_kernel<<<dim3(DM/128, QROWS/128), 256>>>(p_ctx, Wo, bo, nullptr, p_x, QROWS, DM, DM, 0);

    // 10. y = LN_ff(x)
    ln_kernel<<<QROWS, 256>>>(p_x, g_ff, b_ff, p_y);

    // 11. h = gelu(y @ W1 + b1)
    sgemm_kernel<<<dim3(DFF/128, QROWS/128), 256>>>(p_y, W1, b1, nullptr, p_h, QROWS, DFF, DM, 1);

    // 12. out = h @ W2 + b2 + x
    sgemm_kernel<<<dim3(DM/128, QROWS/128), 256>>>(p_h, W2, b2, p_x, out, QROWS, DM, DFF, 2);
}

// round 2
// speedup vs baseline: 2.9356x; 2.9356x over previous
#include <cuda_runtime.h>
#include <math.h>
#include <stdint.h>

// Problem constants
#define BBATCH 8
#define SQLEN  256
#define SKVLEN 1024
#define DMODEL 1024
#define NHEADS 16
#define DHEAD  64
#define DFFN   4096

#define QROWS  (BBATCH*SQLEN)    // 2048
#define KVROWS (BBATCH*SKVLEN)   // 8192
#define OUT_ELEMS  ((size_t)QROWS*DMODEL)
#define ATTN_ELEMS ((size_t)BBATCH*NHEADS*SQLEN*SKVLEN)

// ----------------------------- scratch ---------------------------------
__device__ float g_qln [QROWS*DMODEL];
__device__ float g_kvln[KVROWS*DMODEL];
__device__ float g_Qh  [QROWS*DMODEL];     // [b][h][sq][dk]
__device__ float g_Kh  [KVROWS*DMODEL];    // [b][h][skv][dk]
__device__ float g_Vt  [KVROWS*DMODEL];    // [b][h][dk][skv]
__device__ float g_ctx [QROWS*DMODEL];
__device__ float g_x   [QROWS*DMODEL];
__device__ float g_y   [QROWS*DMODEL];
__device__ float g_h   [QROWS*DFFN];
__device__ float g_Wqt[DMODEL*DMODEL];
__device__ float g_Wkt[DMODEL*DMODEL];
__device__ float g_Wvt[DMODEL*DMODEL];
__device__ float g_Wot[DMODEL*DMODEL];
__device__ float g_W1t[DFFN*DMODEL];
__device__ float g_W2t[DMODEL*DFFN];
__device__ float g_attn_fb[BBATCH*NHEADS*SQLEN*SKVLEN];

// ----------------------------- transpose: Wt[n][k] = W[k][n] ------------
__global__ void __launch_bounds__(256) transpose_kernel(const float* __restrict__ W,
                                                        float* __restrict__ Wt,
                                                        int K, int N) {
    __shared__ float t[32][33];
    const int n0 = blockIdx.x * 32, k0 = blockIdx.y * 32;
    const int x = threadIdx.x & 31, y = threadIdx.x >> 5;
    #pragma unroll
    for (int i = 0; i < 32; i += 8)
        t[y + i][x] = W[(size_t)(k0 + y + i) * N + n0 + x];
    __syncthreads();
    #pragma unroll
    for (int i = 0; i < 32; i += 8)
        Wt[(size_t)(n0 + y + i) * K + k0 + x] = t[x][y + i];
}

// ----------------------------- LayerNorm --------------------------------
__global__ void __launch_bounds__(256) ln_kernel(const float* __restrict__ x,
                                                 const float* __restrict__ g,
                                                 const float* __restrict__ b,
                                                 float* __restrict__ y) {
    __shared__ float ssum[256];
    __shared__ float ssq [256];
    const int row = blockIdx.x;
    const int tid = threadIdx.x;
    const float4 xv = ((const float4*)(x + (size_t)row*DMODEL))[tid];
    ssum[tid] = xv.x + xv.y + xv.z + xv.w;
    ssq [tid] = xv.x*xv.x + xv.y*xv.y + xv.z*xv.z + xv.w*xv.w;
    __syncthreads();
    for (int st = 128; st > 0; st >>= 1) {
        if (tid < st) { ssum[tid] += ssum[tid+st]; ssq[tid] += ssq[tid+st]; }
        __syncthreads();
    }
    const float mu  = ssum[0] * (1.0f/DMODEL);
    const float var = ssq[0]  * (1.0f/DMODEL) - mu*mu;
    const float inv = rsqrtf(var + 1e-5f);
    const float4 gv = ((const float4*)g)[tid];
    const float4 bv = ((const float4*)b)[tid];
    float4 o;
    o.x = (xv.x - mu)*inv*gv.x + bv.x;
    o.y = (xv.y - mu)*inv*gv.y + bv.y;
    o.z = (xv.z - mu)*inv*gv.z + bv.z;
    o.w = (xv.w - mu)*inv*gv.w + bv.w;
    ((float4*)(y + (size_t)row*DMODEL))[tid] = o;
}

// ----------------------------- softmax (rows of 1024, in place) ---------
__global__ void __launch_bounds__(256) softmax_kernel(float* __restrict__ attn) {
    __shared__ float red[256];
    const size_t row = blockIdx.x;
    float4* p = (float4*)(attn + row*(size_t)SKVLEN);
    const int tid = threadIdx.x;
    float4 v = p[tid];
    float m = fmaxf(fmaxf(v.x, v.y), fmaxf(v.z, v.w));
    red[tid] = m; __syncthreads();
    for (int st = 128; st > 0; st >>= 1) {
        if (tid < st) red[tid] = fmaxf(red[tid], red[tid+st]);
        __syncthreads();
    }
    m = red[0];
    __syncthreads();
    v.x = __expf(v.x - m); v.y = __expf(v.y - m);
    v.z = __expf(v.z - m); v.w = __expf(v.w - m);
    red[tid] = v.x + v.y + v.z + v.w; __syncthreads();
    for (int st = 128; st > 0; st >>= 1) {
        if (tid < st) red[tid] += red[tid+st];
        __syncthreads();
    }
    const float inv = 1.0f / red[0];
    v.x *= inv; v.y *= inv; v.z *= inv; v.w *= inv;
    p[tid] = v;
}

// ----------------------------- tf32 MMA helpers --------------------------
__device__ __forceinline__ uint32_t f2tf32(uint32_t bits) {
    uint32_t r;
    asm("cvt.rna.tf32.f32 %0, %1;" : "=r"(r) : "f"(__uint_as_float(bits)));
    return r;
}

__device__ __forceinline__ void ldsm4(uint32_t (&d)[4], uint32_t addr) {
    asm volatile("ldmatrix.sync.aligned.m8n8.x4.shared.b16 {%0,%1,%2,%3}, [%4];"
        : "=r"(d[0]), "=r"(d[1]), "=r"(d[2]), "=r"(d[3]) : "r"(addr));
}

__device__ __forceinline__ void mma_tf32(float (&c)[4], const uint32_t (&a)[4],
                                         const uint32_t* b) {
    asm volatile("mma.sync.aligned.m16n8k8.row.col.f32.tf32.tf32.f32 "
        "{%0,%1,%2,%3},{%4,%5,%6,%7},{%8,%9},{%0,%1,%2,%3};"
        : "+f"(c[0]), "+f"(c[1]), "+f"(c[2]), "+f"(c[3])
        : "r"(a[0]), "r"(a[1]), "r"(a[2]), "r"(a[3]), "r"(b[0]), "r"(b[1]));
}

// Epilogue modes:
// 0: C[row*N+col] = v + bias[col]
// 1: gelu(v + bias[col])
// 2: v + bias[col] + res[row*N+col]
// 3: Q head split (seq 256):  Qh[b][h][sq][dk]
// 4: K head split (seq 1024): Kh[b][h][skv][dk]
// 5: V head split, transposed: Vt[b][h][dk][skv]
// 6: scores: attn[bz][row][col] = v * 0.125
// 7: ctx: row-major [b*SQ+row][h*64+col]
template<int MODE>
__device__ __forceinline__ void store_elem(float* __restrict__ C,
                                           const float* __restrict__ bias,
                                           const float* __restrict__ res,
                                           int N, int bz, int row, int col, float v) {
    if (MODE == 0) {
        C[(size_t)row*N + col] = v + bias[col];
    } else if (MODE == 1) {
        float x = v + bias[col];
        C[(size_t)row*N + col] = 0.5f * x * (1.0f + erff(x * 0.70710678118654752f));
    } else if (MODE == 2) {
        C[(size_t)row*N + col] = v + bias[col] + res[(size_t)row*N + col];
    } else if (MODE == 3) {
        size_t idx = (size_t)(row >> 8)*(NHEADS*SQLEN*DHEAD) + (size_t)(col >> 6)*(SQLEN*DHEAD)
                   + (size_t)(row & 255)*DHEAD + (col & 63);
        C[idx] = v + bias[col];
    } else if (MODE == 4) {
        size_t idx = (size_t)(row >> 10)*(NHEADS*SKVLEN*DHEAD) + (size_t)(col >> 6)*(SKVLEN*DHEAD)
                   + (size_t)(row & 1023)*DHEAD + (col & 63);
        C[idx] = v + bias[col];
    } else if (MODE == 5) {
        size_t idx = (size_t)(row >> 10)*(NHEADS*DHEAD*SKVLEN) + (size_t)(col >> 6)*(DHEAD*SKVLEN)
                   + (size_t)(col & 63)*SKVLEN + (row & 1023);
        C[idx] = v + bias[col];
    } else if (MODE == 6) {
        C[(size_t)bz*(SQLEN*SKVLEN) + (size_t)row*SKVLEN + col] = v * 0.125f;
    } else if (MODE == 7) {
        size_t r = (size_t)(bz >> 4)*SQLEN + row;
        size_t c = (size_t)(bz & 15)*DHEAD + col;
        C[r*DMODEL + c] = v;
    }
}

// ---------------- tf32 NT GEMM: C = A[M,K] * B[N,K]^T (+epilogue) -------
// BK=16, 2-stage cp.async pipeline, 256 threads (8 warps).
template<int BM, int BN, int WM, int WN, int MODE>
__global__ void __launch_bounds__(256, 2) mma_nt_kernel(
    const float* __restrict__ Ag, const float* __restrict__ Bg,
    const float* __restrict__ bias, const float* __restrict__ res,
    float* __restrict__ Cg, int M, int N, int K,
    long sA, long sB)
{
    constexpr int AST = 20;                 // 16 + 4 pad floats
    constexpr int MT = BM / (WM * 16);
    constexpr int NT = BN / (WN * 8);
    __shared__ __align__(16) float As[2][BM][AST];
    __shared__ __align__(16) float Bs[2][BN][AST];

    const int tid  = threadIdx.x;
    const int warp = tid >> 5, lane = tid & 31;
    const int wm0 = (warp % WM) * (BM / WM);
    const int wn0 = (warp / WM) * (BN / WN);
    const int bm0 = blockIdx.y * BM;
    const int bn0 = blockIdx.x * BN;
    const int bz  = blockIdx.z;
    const float* A = Ag + (size_t)bz * sA;
    const float* B = Bg + (size_t)bz * sB;

    const uint32_t sA32 = (uint32_t)__cvta_generic_to_shared(&As[0][0][0]);
    const uint32_t sB32 = (uint32_t)__cvta_generic_to_shared(&Bs[0][0][0]);

    float acc[MT][NT][4];
    #pragma unroll
    for (int i = 0; i < MT; ++i)
        #pragma unroll
        for (int j = 0; j < NT; ++j)
            { acc[i][j][0]=0.f; acc[i][j][1]=0.f; acc[i][j][2]=0.f; acc[i][j][3]=0.f; }

    const int KT = K >> 4;

    auto prefetch = [&](int buf, int kt) {
        const float* Ak = A + (kt << 4);
        for (int i = tid; i < BM*4; i += 256) {
            int r = i >> 2, c = i & 3;
            uint32_t dst = sA32 + (uint32_t)(((buf*BM + r)*AST + c*4) * 4);
            const float* src = Ak + (size_t)(bm0 + r)*K + c*4;
            asm volatile("cp.async.cg.shared.global [%0], [%1], 16;" :: "r"(dst), "l"(src));
        }
        const float* Bk = B + (kt << 4);
        for (int i = tid; i < BN*4; i += 256) {
            int r = i >> 2, c = i & 3;
            uint32_t dst = sB32 + (uint32_t)(((buf*BN + r)*AST + c*4) * 4);
            const float* src = Bk + (size_t)(bn0 + r)*K + c*4;
            asm volatile("cp.async.cg.shared.global [%0], [%1], 16;" :: "r"(dst), "l"(src));
        }
        asm volatile("cp.async.commit_group;");
    };

    prefetch(0, 0);

    for (int kt = 0; kt < KT; ++kt) {
        const int buf = kt & 1;
        if (kt + 1 < KT) {
            prefetch(buf ^ 1, kt + 1);
            asm volatile("cp.async.wait_group 1;");
        } else {
            asm volatile("cp.async.wait_group 0;");
        }
        __syncthreads();

        #pragma unroll
        for (int ks = 0; ks < 2; ++ks) {
            uint32_t af[MT][4];
            uint32_t bf[NT][2];
            const int lr = lane & 15;
            const int lc = (lane >> 4) * 4;
            #pragma unroll
            for (int mt = 0; mt < MT; ++mt) {
                uint32_t addr = sA32 + (uint32_t)((((buf*BM) + wm0 + mt*16 + lr)*AST + ks*8 + lc) * 4);
                ldsm4(af[mt], addr);
                af[mt][0] = f2tf32(af[mt][0]); af[mt][1] = f2tf32(af[mt][1]);
                af[mt][2] = f2tf32(af[mt][2]); af[mt][3] = f2tf32(af[mt][3]);
            }
            const int br = (lane & 7) + ((lane & 16) ? 8 : 0);
            const int bc = (lane & 8) ? 4 : 0;
            #pragma unroll
            for (int nt2 = 0; nt2 < NT/2; ++nt2) {
                uint32_t d[4];
                uint32_t addr = sB32 + (uint32_t)((((buf*BN) + wn0 + nt2*16 + br)*AST + ks*8 + bc) * 4);
                ldsm4(d, addr);
                bf[nt2*2  ][0] = f2tf32(d[0]); bf[nt2*2  ][1] = f2tf32(d[1]);
                bf[nt2*2+1][0] = f2tf32(d[2]); bf[nt2*2+1][1] = f2tf32(d[3]);
            }
            #pragma unroll
            for (int mt = 0; mt < MT; ++mt)
                #pragma unroll
                for (int nt = 0; nt < NT; ++nt)
                    mma_tf32(acc[mt][nt], af[mt], bf[nt]);
        }
        __syncthreads();
    }

    // epilogue
    const int g = lane >> 2, t = lane & 3;
    #pragma unroll
    for (int mt = 0; mt < MT; ++mt) {
        #pragma unroll
        for (int nt = 0; nt < NT; ++nt) {
            const int r0 = bm0 + wm0 + mt*16 + g;
            const int c0 = bn0 + wn0 + nt*8 + t*2;
            store_elem<MODE>(Cg, bias, res, N, bz, r0,     c0,     acc[mt][nt][0]);
            store_elem<MODE>(Cg, bias, res, N, bz, r0,     c0 + 1, acc[mt][nt][1]);
            store_elem<MODE>(Cg, bias, res, N, bz, r0 + 8, c0,     acc[mt][nt][2]);
            store_elem<MODE>(Cg, bias, res, N, bz, r0 + 8, c0 + 1, acc[mt][nt][3]);
        }
    }
}

// ----------------------------- launch ------------------------------------
extern "C" void kernel_launch(void* const* d_in, const int* in_sizes, int n_in,
                              void* d_out, int out_size) {
    const float* memory = (const float*)d_in[0];
    const float* q      = (const float*)d_in[1];
    const float* Wq = (const float*)d_in[2];  const float* bq = (const float*)d_in[3];
    const float* Wk = (const float*)d_in[4];  const float* bk = (const float*)d_in[5];
    const float* Wv = (const float*)d_in[6];  const float* bv = (const float*)d_in[7];
    const float* Wo = (const float*)d_in[8];  const float* bo = (const float*)d_in[9];
    const float* g_kv = (const float*)d_in[10]; const float* b_kv = (const float*)d_in[11];
    const float* g_q  = (const float*)d_in[12]; const float* b_q  = (const float*)d_in[13];
    const float* g_ff = (const float*)d_in[14]; const float* b_ff = (const float*)d_in[15];
    const float* W1 = (const float*)d_in[16]; const float* b1 = (const float*)d_in[17];
    const float* W2 = (const float*)d_in[18]; const float* b2 = (const float*)d_in[19];

    float *p_qln, *p_kvln, *p_Qh, *p_Kh, *p_Vt, *p_ctx, *p_x, *p_y, *p_h;
    float *p_Wqt, *p_Wkt, *p_Wvt, *p_Wot, *p_W1t, *p_W2t, *p_attn_fb;
    cudaGetSymbolAddress((void**)&p_qln,  g_qln);
    cudaGetSymbolAddress((void**)&p_kvln, g_kvln);
    cudaGetSymbolAddress((void**)&p_Qh,   g_Qh);
    cudaGetSymbolAddress((void**)&p_Kh,   g_Kh);
    cudaGetSymbolAddress((void**)&p_Vt,   g_Vt);
    cudaGetSymbolAddress((void**)&p_ctx,  g_ctx);
    cudaGetSymbolAddress((void**)&p_x,    g_x);
    cudaGetSymbolAddress((void**)&p_y,    g_y);
    cudaGetSymbolAddress((void**)&p_h,    g_h);
    cudaGetSymbolAddress((void**)&p_Wqt,  g_Wqt);
    cudaGetSymbolAddress((void**)&p_Wkt,  g_Wkt);
    cudaGetSymbolAddress((void**)&p_Wvt,  g_Wvt);
    cudaGetSymbolAddress((void**)&p_Wot,  g_Wot);
    cudaGetSymbolAddress((void**)&p_W1t,  g_W1t);
    cudaGetSymbolAddress((void**)&p_W2t,  g_W2t);
    cudaGetSymbolAddress((void**)&p_attn_fb, g_attn_fb);

    float* out = (float*)d_out;
    float* attn = ((size_t)out_size >= OUT_ELEMS + ATTN_ELEMS) ? (out + OUT_ELEMS)
                                                               : p_attn_fb;

    // 0. weight transposes (NT layout)
    transpose_kernel<<<dim3(32, 32), 256>>>(Wq, p_Wqt, DMODEL, DMODEL);
    transpose_kernel<<<dim3(32, 32), 256>>>(Wk, p_Wkt, DMODEL, DMODEL);
    transpose_kernel<<<dim3(32, 32), 256>>>(Wv, p_Wvt, DMODEL, DMODEL);
    transpose_kernel<<<dim3(32, 32), 256>>>(Wo, p_Wot, DMODEL, DMODEL);
    transpose_kernel<<<dim3(128, 32), 256>>>(W1, p_W1t, DMODEL, DFFN);
    transpose_kernel<<<dim3(32, 128), 256>>>(W2, p_W2t, DFFN, DMODEL);

    // 1-2. pre-norms
    ln_kernel<<<KVROWS, 256>>>(memory, g_kv, b_kv, p_kvln);
    ln_kernel<<<QROWS,  256>>>(q,      g_q,  b_q,  p_qln);

    // 3-5. QKV projections (head-split epilogues)
    mma_nt_kernel<128,128,2,4,3><<<dim3(8, 16), 256>>>(p_qln,  p_Wqt, bq, nullptr, p_Qh, QROWS,  DMODEL, DMODEL, 0, 0);
    mma_nt_kernel<128,128,2,4,4><<<dim3(8, 64), 256>>>(p_kvln, p_Wkt, bk, nullptr, p_Kh, KVROWS, DMODEL, DMODEL, 0, 0);
    mma_nt_kernel<128,128,2,4,5><<<dim3(8, 64), 256>>>(p_kvln, p_Wvt, bv, nullptr, p_Vt, KVROWS, DMODEL, DMODEL, 0, 0);

    // 6. scores: per (b,h): [256,1024] = Qh[bh] * Kh[bh]^T, *0.125
    mma_nt_kernel<128,128,2,4,6><<<dim3(8, 2, BBATCH*NHEADS), 256>>>(
        p_Qh, p_Kh, nullptr, nullptr, attn, SQLEN, SKVLEN, DHEAD,
        (long)SQLEN*DHEAD, (long)SKVLEN*DHEAD);

    // 7. softmax in place
    softmax_kernel<<<BBATCH*NHEADS*SQLEN, 256>>>(attn);

    // 8. ctx: per (b,h): [256,64] = attn[bh] * Vt[bh]^T  -> row-major ctx
    mma_nt_kernel<128,64,4,2,7><<<dim3(1, 2, BBATCH*NHEADS), 256>>>(
        attn, p_Vt, nullptr, nullptr, p_ctx, SQLEN, DHEAD, SKVLEN,
        (long)SQLEN*SKVLEN, (long)DHEAD*SKVLEN);

    // 9. x = ctx @ Wo + bo
    mma_nt_kernel<128,128,2,4,0><<<dim3(8, 16), 256>>>(p_ctx, p_Wot, bo, nullptr, p_x, QROWS, DMODEL, DMODEL, 0, 0);

    // 10. y = LN_ff(x)
    ln_kernel<<<QROWS, 256>>>(p_x, g_ff, b_ff, p_y);

    // 11. h = gelu(y @ W1 + b1)
    mma_nt_kernel<128,128,2,4,1><<<dim3(32, 16), 256>>>(p_y, p_W1t, b1, nullptr, p_h, QROWS, DFFN, DMODEL, 0, 0);

    // 12. out = h @ W2 + b2 + x
    mma_nt_kernel<128,128,2,4,2><<<dim3(8, 16), 256>>>(p_h, p_W2t, b2, p_x, out, QROWS, DMODEL, DFFN, 0, 0);
}